// round 16
// baseline (speedup 1.0000x reference)
#include <cuda_runtime.h>

// Problem constants (fixed shapes)
#define NB   64
#define NH   1024
#define NS   512
#define W    8                  // steps per smem window
#define NWIN (NS / W)           // 64 windows
#define PITCH 9                 // floats per row slice (8 + 1 pad -> conflict-free LDS)
#define EPL  32                 // elements per lane (NH / 32)

#define BUF_FLOATS  (NH * PITCH)            // 9216 floats per buffer
#define SM_MASK_OFF (2 * BUF_FLOATS)        // 18432
#define SMEM_FLOATS (SM_MASK_OFF + NS)      // 18944
#define SMEM_BYTES  (SMEM_FLOATS * 4)       // 75776 B

__device__ __forceinline__ float clip1(float x) {
    return fminf(fmaxf(x, -1.0f), 1.0f);
}

// One warp per batch. No __syncthreads anywhere: the block reduction is a pure
// warp butterfly whose result lands in every lane (no smem roundtrip, no
// barrier STS-drain tax, no inter-warp skew).
extern "C" __global__ void __launch_bounds__(32, 1)
orth_scan_kernel(const float* __restrict__ tree,
                 const float* __restrict__ seq,
                 const float* __restrict__ mask,
                 float* __restrict__ out)
{
    extern __shared__ float sm[];
    float* buf0 = sm;                   // [NH][PITCH] window buffer A
    float* buf1 = sm + BUF_FLOATS;      // window buffer B
    float* msm  = sm + SM_MASK_OFF;     // [NS]

    const int lane = threadIdx.x;
    const int b    = blockIdx.x;
    const float* seqb = seq + (size_t)b * NH * NS;

    // ---- carry h: lane owns rows {j*32 + lane} ----
    float h[EPL];
    #pragma unroll
    for (int j = 0; j < EPL; j++)
        h[j] = tree[b * NH + j * 32 + lane];

    // ---- mask -> smem (coalesced float4) ----
    #pragma unroll
    for (int k = 0; k < 4; k++) {
        float4 v = *(const float4*)(mask + b * NS + k * 128 + lane * 4);
        *(float4*)(msm + k * 128 + lane * 4) = v;
    }

    // Staging geometry: group g = 16 rows x 2 chunks. lane -> (row g*16 + lane/2,
    // chunk lane&1). One warp-LDG = 16 rows x 32B = 16 full sectors (100% eff).
    const int lr = lane >> 1;   // 0..15 row-within-group
    const int lc = lane & 1;    // 0..1  t-chunk (4 floats)

    // ---- stage window 0 into buf0 ----
    #pragma unroll 4
    for (int g = 0; g < 64; g++) {
        int r = g * 16 + lr;
        float4 v = *(const float4*)(seqb + (size_t)r * NS + 4 * lc);
        float* d = buf0 + r * PITCH + 4 * lc;
        d[0] = v.x; d[1] = v.y; d[2] = v.z; d[3] = v.w;
    }

    // ---- preload pipeline: window 1 groups 0..15 into stg slots 0..15 ----
    float4 stg[16];
    #pragma unroll
    for (int k = 0; k < 16; k++) {
        int r = k * 16 + lr;
        stg[k] = *(const float4*)(seqb + (size_t)r * NS + W + 4 * lc);
    }
    __syncwarp();

    // ---- s0 + initial reduce: dot(h0,s0), |h0|^2, |s0|^2 ----
    float s[EPL];
    #pragma unroll
    for (int j = 0; j < EPL; j++)
        s[j] = buf0[(j * 32 + lane) * PITCH + 0];

    float dot, hh, ss;
    {
        float dp[4] = {0,0,0,0}, hp[4] = {0,0,0,0}, sp[4] = {0,0,0,0};
        #pragma unroll
        for (int j = 0; j < EPL; j++) {
            dp[j & 3] = fmaf(h[j], s[j], dp[j & 3]);
            hp[j & 3] = fmaf(h[j], h[j], hp[j & 3]);
            sp[j & 3] = fmaf(s[j], s[j], sp[j & 3]);
        }
        float pd = (dp[0] + dp[1]) + (dp[2] + dp[3]);
        float ph = (hp[0] + hp[1]) + (hp[2] + hp[3]);
        float ps = (sp[0] + sp[1]) + (sp[2] + sp[3]);
        #pragma unroll
        for (int mm = 16; mm > 0; mm >>= 1) {
            pd += __shfl_xor_sync(0xffffffffu, pd, mm);
            ph += __shfl_xor_sync(0xffffffffu, ph, mm);
            ps += __shfl_xor_sync(0xffffffffu, ps, mm);
        }
        dot = pd; hh = ph; ss = ps;
    }

    // ---- main scan ----
    // Steady-state staging stream (per local): STS window win+1 groups [8l,8l+8)
    // (loaded 2 locals ago), then LDG: locals 0..5 -> window win+1 groups
    // [8l+16, 8l+24), locals 6..7 -> window win+2 groups [8(l-6), +8).
    // 2-buffer proof: window w written during locals [8w-8, 8w-1], read
    // [8w, 8w+7], next writer (w+2) starts at 8w+8.
    for (int win = 0; win < NWIN; ++win) {
        float* cb = (win & 1) ? buf1 : buf0;   // current window
        float* nb = (win & 1) ? buf0 : buf1;   // next window
        const bool stage1 = (win + 1 < NWIN);
        const bool stage2 = (win + 2 < NWIN);

        #pragma unroll
        for (int l = 0; l < W; ++l) {
            const int t = win * W + l;
            const float m = msm[t];

            // cos = dot / max(sqrt(hh*ss), 1e-8) == dot * rsqrt(max(hh*ss,1e-16))
            const float cosv = dot * rsqrtf(fmaxf(hh * ss, 1e-16f));

            // update: h = clip(h + (s - h*cos)*m)   (FMNMX rides the alu pipe)
            #pragma unroll
            for (int j = 0; j < EPL; j++)
                h[j] = clip1(fmaf(m, fmaf(-cosv, h[j], s[j]), h[j]));

            const int sb = (l & 1) * 8;   // stg ring: even locals slots 0..7, odd 8..15

            // STS: window win+1 groups 8l..8l+7 (scatter, reg-scoreboarded vs LDG below)
            if (stage1) {
                #pragma unroll
                for (int k = 0; k < 8; k++) {
                    int r = (8 * l + k) * 16 + lr;
                    float* d = nb + r * PITCH + 4 * lc;
                    float4 v = stg[sb + k];
                    d[0] = v.x; d[1] = v.y; d[2] = v.z; d[3] = v.w;
                }
            }
            // LDG into the slots just freed
            if (l < 6) {
                if (stage1) {
                    #pragma unroll
                    for (int k = 0; k < 8; k++) {
                        int r = (8 * l + 16 + k) * 16 + lr;
                        stg[sb + k] = *(const float4*)(
                            seqb + (size_t)r * NS + (size_t)(win + 1) * W + 4 * lc);
                    }
                }
            } else {
                if (stage2) {
                    #pragma unroll
                    for (int k = 0; k < 8; k++) {
                        int r = (8 * (l - 6) + k) * 16 + lr;
                        stg[sb + k] = *(const float4*)(
                            seqb + (size_t)r * NS + (size_t)(win + 2) * W + 4 * lc);
                    }
                }
            }
            // cross-lane smem visibility for the window we just finished storing
            if (l == W - 1) __syncwarp();

            if (t < NS - 1) {
                // prefetch s_{t+1} (conflict-free: pitch 9 odd, lane stride 9)
                float sn[EPL];
                const float* srcb = (l < W - 1) ? cb : nb;
                const int    tt   = (l < W - 1) ? (l + 1) : 0;
                #pragma unroll
                for (int j = 0; j < EPL; j++)
                    sn[j] = srcb[(j * 32 + lane) * PITCH + tt];

                // partials for step t+1 (updated h with s_{t+1})
                float dp[4] = {0,0,0,0}, hp[4] = {0,0,0,0}, sp[4] = {0,0,0,0};
                #pragma unroll
                for (int j = 0; j < EPL; j++) {
                    dp[j & 3] = fmaf(h[j], sn[j], dp[j & 3]);
                    hp[j & 3] = fmaf(h[j], h[j], hp[j & 3]);
                    sp[j & 3] = fmaf(sn[j], sn[j], sp[j & 3]);
                }
                float pd = (dp[0] + dp[1]) + (dp[2] + dp[3]);
                float ph = (hp[0] + hp[1]) + (hp[2] + hp[3]);
                float ps = (sp[0] + sp[1]) + (sp[2] + sp[3]);
                #pragma unroll
                for (int mm = 16; mm > 0; mm >>= 1) {
                    pd += __shfl_xor_sync(0xffffffffu, pd, mm);
                    ph += __shfl_xor_sync(0xffffffffu, ph, mm);
                    ps += __shfl_xor_sync(0xffffffffu, ps, mm);
                }
                dot = pd; hh = ph; ss = ps;
                #pragma unroll
                for (int j = 0; j < EPL; j++) s[j] = sn[j];
            }
        }
    }

    // ---- write final h (coalesced) ----
    #pragma unroll
    for (int j = 0; j < EPL; j++)
        out[b * NH + j * 32 + lane] = h[j];
}

extern "C" void kernel_launch(void* const* d_in, const int* in_sizes, int n_in,
                              void* d_out, int out_size)
{
    const float* tree = nullptr;
    const float* seq  = nullptr;
    const float* mask = nullptr;
    for (int i = 0; i < n_in; i++) {
        if (in_sizes[i] == NB * NH)           tree = (const float*)d_in[i];
        else if (in_sizes[i] == NB * NH * NS) seq  = (const float*)d_in[i];
        else if (in_sizes[i] == NB * NS)      mask = (const float*)d_in[i];
    }
    float* out = (float*)d_out;

    cudaFuncSetAttribute(orth_scan_kernel,
                         cudaFuncAttributeMaxDynamicSharedMemorySize, SMEM_BYTES);
    orth_scan_kernel<<<NB, 32, SMEM_BYTES>>>(tree, seq, mask, out);
}